// round 7
// baseline (speedup 1.0000x reference)
#include <cuda_runtime.h>
#include <cuda_bf16.h>
#include <math.h>
#include <stdint.h>

#define HID     256
#define NT      31
#define NTREES  4096
#define NNODES  (NTREES*NT)       // 126976
#define NE_TREE 30
#define NE_HALF (NTREES*NE_TREE)  // 122880
#define VOCAB   780

// ---------------- scratch (static device globals; no allocation) ----------------
__device__ float g_s [NNODES*HID];
__device__ float g_rm[NNODES*HID];
__device__ float g_M [32768*HID];
__device__ float g_Pz[VOCAB*HID];
__device__ float g_Ph[VOCAB*HID];
__device__ float g_Pr[VOCAB*HID];
__device__ float g_Pf[VOCAB*HID];
__device__ float g_M0 [VOCAB*HID];
__device__ float g_MU0[VOCAB*HID];
__device__ __nv_bfloat16 g_Whi[8*HID*HID];   // transposed [n][k] bf16 hi
__device__ __nv_bfloat16 g_Wlo[8*HID*HID];   // transposed [n][k] bf16 lo

__device__ __forceinline__ float sigf(float x){ return 1.0f/(1.0f+expf(-x)); }

__device__ __forceinline__ uint32_t smem_u32(const void* p){
    uint32_t a;
    asm("{ .reg .u64 t; cvta.to.shared.u64 t, %1; cvt.u32.u64 %0, t; }" : "=r"(a) : "l"(p));
    return a;
}
__device__ __forceinline__ void ldsm_x4(uint32_t a, uint32_t* r){
    asm volatile("ldmatrix.sync.aligned.m8n8.x4.shared.b16 {%0,%1,%2,%3}, [%4];"
        : "=r"(r[0]),"=r"(r[1]),"=r"(r[2]),"=r"(r[3]) : "r"(a));
}
__device__ __forceinline__ void mma_bf16(float* d, const uint32_t* a, const uint32_t* b){
    asm volatile("mma.sync.aligned.m16n8k16.row.col.f32.bf16.bf16.f32 "
        "{%0,%1,%2,%3}, {%4,%5,%6,%7}, {%8,%9}, {%0,%1,%2,%3};"
        : "+f"(d[0]),"+f"(d[1]),"+f"(d[2]),"+f"(d[3])
        : "r"(a[0]),"r"(a[1]),"r"(a[2]),"r"(a[3]), "r"(b[0]),"r"(b[1]));
}
__device__ __forceinline__ void cp16(uint32_t dst, const void* src){
    asm volatile("cp.async.cg.shared.global [%0], [%1], 16;" :: "r"(dst), "l"(src));
}
#define CP_COMMIT() asm volatile("cp.async.commit_group;" ::: "memory")
#define CP_WAIT0()  asm volatile("cp.async.wait_group 0;" ::: "memory")
#define SWZ(o) ((o) ^ (((o) >> 3) & 0x70))

__device__ __forceinline__ void cvt_split(float4 v, uint2& hi, uint2& lo){
    __nv_bfloat162 h01 = __floats2bfloat162_rn(v.x, v.y);
    __nv_bfloat162 h23 = __floats2bfloat162_rn(v.z, v.w);
    float lx = v.x - __bfloat162float(h01.x);
    float ly = v.y - __bfloat162float(h01.y);
    float lz = v.z - __bfloat162float(h23.x);
    float lw = v.w - __bfloat162float(h23.y);
    __nv_bfloat162 l01 = __floats2bfloat162_rn(lx, ly);
    __nv_bfloat162 l23 = __floats2bfloat162_rn(lz, lw);
    hi = make_uint2(*(uint32_t*)&h01, *(uint32_t*)&h23);
    lo = make_uint2(*(uint32_t*)&l01, *(uint32_t*)&l23);
}

// ==================================================================
// DUAL GEMM: accZ = A1[node]@Wmat1, accH = A2[node]@Wmat2 (bf16-split x3)
// epilogue: z=sig(accZ+Pz[w]), h=tanh(accH+Ph[w]), m=(1-z)*A1[node]+z*h
//   BU (td=0): out[tree*NE_TREE+base-1+jj] = m
//   TD (td=1): g_M[rg]=m; out[NE_HALF+tree*NE_TREE+2*pl + {0,1}] = m
// node = (rg>>aL)*aRS + aBase + (rg&mask).  512 thr, 16 warps (4m x 4n),
// M-tile 128, N-tile 64 (grid.y=4), K-chunk 32, smem 48KB.
// SMEM: A1[0,16K) A2[16K,32K) W1[32K,40K) W2[40K,48K); rows 128B=[hi64|lo64]
// ==================================================================
__global__ void __launch_bounds__(512,1) gemm_dual(
    const float* __restrict__ A1, const float* __restrict__ A2,
    const float* __restrict__ P1, const float* __restrict__ P2,
    int mat1, int mat2,
    int aL, int aRS, int aBase, int R,
    const int* __restrict__ wid, int td, int base,
    float* __restrict__ out)
{
    extern __shared__ char sm[];
    const uint32_t sb = smem_u32(sm);
    const int tid = threadIdx.x, l = tid & 31, w = tid >> 5;
    const int wm = w >> 2, wn = w & 3;
    const int row0 = blockIdx.x * 128, col0 = blockIdx.y * 64;
    const int aMask = (1 << aL) - 1;

    // A loader map: row = tid&127, src = (tid>>7)&1, half = (tid>>8)&1
    const int arow = tid & 127, asrc = (tid >> 7) & 1, ahalf = (tid >> 8) & 1;
    const int argl = row0 + arow;
    const int anode = ((argl >> aL) * aRS) + aBase + (argl & aMask);
    const float* Asrc = (asrc ? A2 : A1) + (size_t)anode * HID;

    // W loader map: 1024 uint4; idx = tid*2+e: mat=(idx>>9), nr=(idx>>3)&63, u=idx&7
    const __nv_bfloat16* WH[2] = { g_Whi + (size_t)mat1*HID*HID, g_Whi + (size_t)mat2*HID*HID };
    const __nv_bfloat16* WL[2] = { g_Wlo + (size_t)mat1*HID*HID, g_Wlo + (size_t)mat2*HID*HID };

    float acc[2][2][2][4];
    #pragma unroll
    for (int a=0;a<2;a++)
        #pragma unroll
        for (int b=0;b<2;b++)
            #pragma unroll
            for (int c=0;c<2;c++)
                #pragma unroll
                for (int q=0;q<4;q++) acc[a][b][c][q]=0.f;

    #pragma unroll 1
    for (int kc = 0; kc < 8; kc++) {
        // W via cp.async
        #pragma unroll
        for (int e = 0; e < 2; e++) {
            int idx = tid*2 + e;
            int mt = idx >> 9, nr = (idx >> 3) & 63, u = idx & 7;
            uint32_t dst = sb + 32768 + mt*8192 + SWZ((uint32_t)(nr*128 + u*16));
            const __nv_bfloat16* s = (u < 4)
                ? WH[mt] + (size_t)(col0+nr)*HID + kc*32 + u*8
                : WL[mt] + (size_t)(col0+nr)*HID + kc*32 + (u-4)*8;
            cp16(dst, s);
        }
        CP_COMMIT();
        // A: 4 float4 -> hi/lo
        #pragma unroll
        for (int i = 0; i < 4; i++) {
            float4 v = *(const float4*)(Asrc + kc*32 + ahalf*16 + i*4);
            uint2 hi, lo; cvt_split(v, hi, lo);
            uint32_t ro = (uint32_t)(arow*128 + ahalf*32 + i*8);
            *(uint2*)(sm + asrc*16384 + SWZ(ro))      = hi;
            *(uint2*)(sm + asrc*16384 + SWZ(ro + 64)) = lo;
        }
        CP_WAIT0();
        __syncthreads();

        #pragma unroll
        for (int ks = 0; ks < 2; ks++) {
            #pragma unroll
            for (int J = 0; J < 2; J++) {
                uint32_t fh[2][4], fl[2][4];
                #pragma unroll
                for (int ms = 0; ms < 2; ms++) {
                    int rrow = wm*32 + ms*16 + (l & 15);
                    int kb   = ks*16 + (l >> 4) * 8;
                    ldsm_x4(sb + J*16384 + SWZ((uint32_t)(rrow*128 + kb*2)),      fh[ms]);
                    ldsm_x4(sb + J*16384 + SWZ((uint32_t)(rrow*128 + 64 + kb*2)), fl[ms]);
                }
                int mi   = l >> 3;
                int nrow = wn*16 + (mi >> 1) * 8 + (l & 7);
                int kb2  = ks*16 + (mi & 1) * 8;
                uint32_t rh[4], rl[4];
                ldsm_x4(sb + 32768 + J*8192 + SWZ((uint32_t)(nrow*128 + kb2*2)),      rh);
                ldsm_x4(sb + 32768 + J*8192 + SWZ((uint32_t)(nrow*128 + 64 + kb2*2)), rl);
                #pragma unroll
                for (int ms = 0; ms < 2; ms++) {
                    mma_bf16(acc[J][ms][0], fh[ms], &rh[0]);
                    mma_bf16(acc[J][ms][0], fh[ms], &rl[0]);
                    mma_bf16(acc[J][ms][0], fl[ms], &rh[0]);
                    mma_bf16(acc[J][ms][1], fh[ms], &rh[2]);
                    mma_bf16(acc[J][ms][1], fh[ms], &rl[2]);
                    mma_bf16(acc[J][ms][1], fl[ms], &rh[2]);
                }
            }
        }
        __syncthreads();
    }

    // ---- fused M epilogue ----
    #pragma unroll
    for (int ms = 0; ms < 2; ms++) {
        #pragma unroll
        for (int rr = 0; rr < 2; rr++) {
            int rg = row0 + wm*32 + ms*16 + rr*8 + (l >> 2);
            int tree = rg >> aL, jj = rg & aMask;
            int node = tree * aRS + aBase + jj;
            int wz = wid[node];
            const float* pz = P1 + (size_t)wz * HID;
            const float* ph = P2 + (size_t)wz * HID;
            const float* srow = A1 + (size_t)node * HID;
            float* orow;
            float* mrow = nullptr;
            if (!td) {
                orow = out + (size_t)(tree*NE_TREE + base - 1 + jj) * HID;
            } else {
                int pl = aBase + jj;   // parent local id
                orow = out + ((size_t)NE_HALF + (size_t)tree*NE_TREE + 2*pl) * HID;
                mrow = g_M + (size_t)rg * HID;
            }
            #pragma unroll
            for (int ns = 0; ns < 2; ns++) {
                int c = col0 + wn*16 + ns*8 + (l & 3)*2;
                #pragma unroll
                for (int cc = 0; cc < 2; cc++) {
                    float z = sigf (acc[0][ms][ns][rr*2+cc] + pz[c+cc]);
                    float h = tanhf(acc[1][ms][ns][rr*2+cc] + ph[c+cc]);
                    float m = (1.f - z) * srow[c+cc] + z * h;
                    if (!td) orow[c+cc] = m;
                    else { mrow[c+cc] = m; orow[c+cc] = m; orow[HID + c+cc] = m; }
                }
            }
        }
    }
}

// ==================================================================
// SINGLE GEMM with fused epilogues. 256 thr, 8 warps (4m x 2n),
// M 128, N 64 (grid.y=4), K-chunk 32, smem 24KB, 2 CTAs/SM.
// modes: 0 C=acc(+bias) [bounds]; 3 BU-R+pair-reduce; 5 TD-R+children;
//        6 C=relu(acc+P[wid[node]]) [bounds]
// ==================================================================
struct GJob {
    const float* A;
    float*       C;
    const float* P;
    const float* bias;
    int mat;
};

__global__ void __launch_bounds__(256,2) gemm_s(
    GJob j0, GJob j1, GJob j2, GJob j3, int mode,
    int aL, int aRS, int aBase, int R,
    const int* __restrict__ wid, int dlev, int base)
{
    extern __shared__ char sm[];
    const uint32_t sb = smem_u32(sm);
    const int tid = threadIdx.x, l = tid & 31, w = tid >> 5;
    const int wm = w >> 1, wn = w & 1;
    const int row0 = blockIdx.x * 128, col0 = blockIdx.y * 64;
    const int aMask = (1 << aL) - 1;

    const GJob j = (blockIdx.z == 0) ? j0 : (blockIdx.z == 1) ? j1
                 : (blockIdx.z == 2) ? j2 : j3;

    const int arow = tid & 127, ahalf = tid >> 7;
    const int argl = row0 + arow;
    const float* Asrc = nullptr;
    if (argl < R) {
        int anode = ((argl >> aL) * aRS) + aBase + (argl & aMask);
        Asrc = j.A + (size_t)anode * HID;
    }
    const __nv_bfloat16* WH = g_Whi + (size_t)j.mat * HID * HID;
    const __nv_bfloat16* WL = g_Wlo + (size_t)j.mat * HID * HID;

    float acc[2][4][4];
    #pragma unroll
    for (int a=0;a<2;a++)
        #pragma unroll
        for (int b=0;b<4;b++)
            #pragma unroll
            for (int q=0;q<4;q++) acc[a][b][q]=0.f;

    #pragma unroll 1
    for (int kc = 0; kc < 8; kc++) {
        #pragma unroll
        for (int e = 0; e < 2; e++) {
            int idx = tid*2 + e;
            int nr = (idx >> 3) & 63, u = idx & 7;
            uint32_t dst = sb + 16384 + SWZ((uint32_t)(nr*128 + u*16));
            const __nv_bfloat16* s = (u < 4)
                ? WH + (size_t)(col0+nr)*HID + kc*32 + u*8
                : WL + (size_t)(col0+nr)*HID + kc*32 + (u-4)*8;
            cp16(dst, s);
        }
        CP_COMMIT();
        #pragma unroll
        for (int i = 0; i < 4; i++) {
            float4 v = Asrc ? *(const float4*)(Asrc + kc*32 + ahalf*16 + i*4)
                            : make_float4(0.f,0.f,0.f,0.f);
            uint2 hi, lo; cvt_split(v, hi, lo);
            uint32_t ro = (uint32_t)(arow*128 + ahalf*32 + i*8);
            *(uint2*)(sm + SWZ(ro))      = hi;
            *(uint2*)(sm + SWZ(ro + 64)) = lo;
        }
        CP_WAIT0();
        __syncthreads();

        #pragma unroll
        for (int ks = 0; ks < 2; ks++) {
            uint32_t fh[2][4], fl[2][4];
            #pragma unroll
            for (int ms = 0; ms < 2; ms++) {
                int rrow = wm*32 + ms*16 + (l & 15);
                int kb   = ks*16 + (l >> 4) * 8;
                ldsm_x4(sb + SWZ((uint32_t)(rrow*128 + kb*2)),      fh[ms]);
                ldsm_x4(sb + SWZ((uint32_t)(rrow*128 + 64 + kb*2)), fl[ms]);
            }
            #pragma unroll
            for (int p = 0; p < 2; p++) {
                int mi   = l >> 3;
                int nrow = wn*32 + p*16 + (mi >> 1) * 8 + (l & 7);
                int kb2  = ks*16 + (mi & 1) * 8;
                uint32_t rh[4], rl[4];
                ldsm_x4(sb + 16384 + SWZ((uint32_t)(nrow*128 + kb2*2)),      rh);
                ldsm_x4(sb + 16384 + SWZ((uint32_t)(nrow*128 + 64 + kb2*2)), rl);
                #pragma unroll
                for (int ms = 0; ms < 2; ms++) {
                    mma_bf16(acc[ms][2*p],   fh[ms], &rh[0]);
                    mma_bf16(acc[ms][2*p],   fh[ms], &rl[0]);
                    mma_bf16(acc[ms][2*p],   fl[ms], &rh[0]);
                    mma_bf16(acc[ms][2*p+1], fh[ms], &rh[2]);
                    mma_bf16(acc[ms][2*p+1], fh[ms], &rl[2]);
                    mma_bf16(acc[ms][2*p+1], fl[ms], &rh[2]);
                }
            }
        }
        __syncthreads();
    }

    // ---- epilogues ----
    #pragma unroll
    for (int ms = 0; ms < 2; ms++) {
        #pragma unroll
        for (int rr = 0; rr < 2; rr++) {
            int rg = row0 + wm*32 + ms*16 + rr*8 + (l >> 2);
            if (mode == 0 || mode == 6) {
                if (rg >= R) continue;
                int node = ((rg >> aL) * aRS) + aBase + (rg & aMask);
                const float* prow = (mode == 6) ? j.P + (size_t)wid[node]*HID : nullptr;
                float* crow = j.C + (size_t)rg * HID;
                #pragma unroll
                for (int ns = 0; ns < 4; ns++) {
                    int c = col0 + wn*32 + ns*8 + (l & 3)*2;
                    float v0 = acc[ms][ns][rr*2+0];
                    float v1 = acc[ms][ns][rr*2+1];
                    if (prow)  { v0 = fmaxf(v0 + prow[c], 0.f); v1 = fmaxf(v1 + prow[c+1], 0.f); }
                    if (j.bias){ v0 += j.bias[c]; v1 += j.bias[c+1]; }
                    *(float2*)(crow + c) = make_float2(v0, v1);
                }
            } else if (mode == 3) {
                int tree = rg >> aL, jj = rg & aMask;
                int node = tree * aRS + aBase + jj;       // edge row in out
                int parent = tree * NT + ((base + jj - 1) >> 1);
                const float* mrow = j.A + (size_t)node * HID;
                const float* prow = j.P + (size_t)wid[parent] * HID;
                float* ds = g_s  + (size_t)parent * HID;
                float* dr = g_rm + (size_t)parent * HID;
                #pragma unroll
                for (int ns = 0; ns < 4; ns++) {
                    int c = col0 + wn*32 + ns*8 + (l & 3)*2;
                    #pragma unroll
                    for (int cc = 0; cc < 2; cc++) {
                        float r = sigf(acc[ms][ns][rr*2+cc] + prow[c+cc]);
                        float m = mrow[c+cc];
                        float mr = m * r;
                        float msum  = m  + __shfl_xor_sync(0xffffffffu, m, 4);
                        float mrsum = mr + __shfl_xor_sync(0xffffffffu, mr, 4);
                        if (!(l & 4)) { ds[c+cc] = msum; dr[c+cc] = mrsum; }
                    }
                }
            } else { // mode 5
                int mask2 = (1 << dlev) - 1;
                int tree = rg >> dlev, q = rg & mask2;
                int pl = mask2 + q;
                int ch = tree * NT + 2*pl + 1;
                const float* mrow = j.A + (size_t)rg * HID;   // g_M
                const float* p0 = j.P + (size_t)wid[ch]   * HID;
                const float* p1 = j.P + (size_t)wid[ch+1] * HID;
                float* s0 = g_s  + (size_t)ch * HID;
                float* r0 = g_rm + (size_t)ch * HID;
                #pragma unroll
                for (int ns = 0; ns < 4; ns++) {
                    int c = col0 + wn*32 + ns*8 + (l & 3)*2;
                    #pragma unroll
                    for (int cc = 0; cc < 2; cc++) {
                        float a  = acc[ms][ns][rr*2+cc];
                        float m  = mrow[c+cc];
                        float ra = sigf(a + p0[c+cc]);
                        float rb = sigf(a + p1[c+cc]);
                        s0[c+cc]       = m;
                        s0[HID + c+cc] = m;
                        r0[c+cc]       = m * ra;
                        r0[HID + c+cc] = m * rb;
                    }
                }
            }
        }
    }
}

// ---------------- weight transpose + bf16 split prep ----------------
__global__ void k_prepw(const float* __restrict__ Wz, const float* __restrict__ Wh,
                        const float* __restrict__ Wr, const float* __restrict__ Ur,
                        const float* __restrict__ Wf)
{
    const float* src;
    switch (blockIdx.x) {
        case 0: src = Wz; break;            case 1: src = Wz + 256*HID; break;
        case 2: src = Wh; break;            case 3: src = Wh + 256*HID; break;
        case 4: src = Wr; break;            case 5: src = Ur; break;
        case 6: src = Wf; break;            default: src = Wf + 256*HID; break;
    }
    int n = threadIdx.x;
    size_t mb = (size_t)blockIdx.x * HID * HID;
    int k0 = blockIdx.y * 32;
    for (int k = k0; k < k0 + 32; k++) {
        float v = src[(size_t)k * HID + n];
        __nv_bfloat16 h = __float2bfloat16(v);
        float lo = v - __bfloat162float(h);
        g_Whi[mb + (size_t)n * HID + k] = h;
        g_Wlo[mb + (size_t)n * HID + k] = __float2bfloat16(lo);
    }
}

// ---------------- structural kernels ----------------
__global__ void k_M0() {
    size_t o = (size_t)blockIdx.x * HID + threadIdx.x;
    g_M0[o] = sigf(g_Pz[o]) * tanhf(g_Ph[o]);
}

__global__ void k_bu_leaf(const int* __restrict__ wid, float* __restrict__ out) {
    int p = blockIdx.x, j = threadIdx.x;
    int tree = p >> 3, q = p & 7;
    int pl = 7 + q;
    int parent = tree * NT + pl;
    int c0 = 2 * pl + 1;
    int child0 = tree * NT + c0;
    int w0 = wid[child0], w1 = wid[child0 + 1];
    float pr = g_Pr[(size_t)wid[parent] * HID + j];
    float m0 = g_M0[(size_t)w0 * HID + j];
    float m1 = g_M0[(size_t)w1 * HID + j];
    float r0 = sigf(pr + g_MU0[(size_t)w0 * HID + j]);
    float r1 = sigf(pr + g_MU0[(size_t)w1 * HID + j]);
    size_t e0 = (size_t)(tree * NE_TREE + c0 - 1) * HID + j;
    out[e0]       = m0;
    out[e0 + HID] = m1;
    size_t po = (size_t)parent * HID + j;
    g_s[po]  = m0 + m1;
    g_rm[po] = m0 * r0 + m1 * r1;
}

__global__ void k_td_root(const int* __restrict__ wid, float* __restrict__ out) {
    int tree = blockIdx.x, j = threadIdx.x;
    int wr = wid[tree * NT];
    float m  = g_M0 [(size_t)wr * HID + j];
    float mu = g_MU0[(size_t)wr * HID + j];
    #pragma unroll
    for (int c = 1; c <= 2; c++) {
        int child = tree * NT + c;
        float r = sigf(g_Pr[(size_t)wid[child] * HID + j] + mu);
        size_t co = (size_t)child * HID + j;
        g_s[co]  = m;
        g_rm[co] = m * r;
        out[(size_t)(NE_HALF + tree * NE_TREE + c - 1) * HID + j] = m;
    }
}

// ---------------- host ----------------
#define SM_DUAL 49152
#define SM_SNG  24576

static inline void launch_s(const GJob* js, int nz, int mode,
                            int aL, int aRS, int aBase, int R,
                            const int* wid, int dlev, int base)
{
    dim3 g((R + 127) / 128, 4, nz);
    gemm_s<<<g, 256, SM_SNG>>>(
        js[0], (nz>1)?js[1]:js[0], (nz>2)?js[2]:js[0], (nz>3)?js[3]:js[0],
        mode, aL, aRS, aBase, R, wid, dlev, base);
}

extern "C" void kernel_launch(void* const* d_in, const int* in_sizes, int n_in,
                              void* d_out, int out_size)
{
    const int*   wid = (const int*)  d_in[0];
    const float* emb = (const float*)d_in[1];
    const float* Wz  = (const float*)d_in[2];
    const float* bz  = (const float*)d_in[3];
    const float* Wh  = (const float*)d_in[4];
    const float* bh  = (const float*)d_in[5];
    const float* Wr  = (const float*)d_in[6];
    const float* Ur  = (const float*)d_in[7];
    const float* bu  = (const float*)d_in[8];
    const float* Wf  = (const float*)d_in[9];
    const float* bf  = (const float*)d_in[10];
    float* out = (float*)d_out;

    float *p_s, *p_rm, *p_M, *p_Pz, *p_Ph, *p_Pr, *p_Pf, *p_M0, *p_MU0;
    cudaGetSymbolAddress((void**)&p_s,   g_s);
    cudaGetSymbolAddress((void**)&p_rm,  g_rm);
    cudaGetSymbolAddress((void**)&p_M,   g_M);
    cudaGetSymbolAddress((void**)&p_Pz,  g_Pz);
    cudaGetSymbolAddress((void**)&p_Ph,  g_Ph);
    cudaGetSymbolAddress((void**)&p_Pr,  g_Pr);
    cudaGetSymbolAddress((void**)&p_Pf,  g_Pf);
    cudaGetSymbolAddress((void**)&p_M0,  g_M0);
    cudaGetSymbolAddress((void**)&p_MU0, g_MU0);

    cudaFuncSetAttribute(gemm_dual, cudaFuncAttributeMaxDynamicSharedMemorySize, SM_DUAL);
    cudaFuncSetAttribute(gemm_s,    cudaFuncAttributeMaxDynamicSharedMemorySize, SM_SNG);

    k_prepw<<<dim3(8, 8), 256>>>(Wz, Wh, Wr, Ur, Wf);

    // vocab tables: 4 GEMMs, one launch
    {
        GJob js[4] = {
            { emb, p_Pz, nullptr, bz, 0 },
            { emb, p_Ph, nullptr, bh, 2 },
            { emb, p_Pr, nullptr, bu, 4 },
            { emb, p_Pf, nullptr, bf, 6 },
        };
        launch_s(js, 4, 0, 0, 1, 0, VOCAB, wid, 0, 0);
    }
    k_M0<<<VOCAB, HID>>>();
    {
        GJob js[1] = { { p_M0, p_MU0, nullptr, nullptr, 5 } };
        launch_s(js, 1, 0, 0, 1, 0, VOCAB, wid, 0, 0);
    }

    // ---- bottom-up ----
    k_bu_leaf<<<NTREES * 8, HID>>>(wid, out);
    for (int d = 2; d >= 0; d--) {
        int L = d + 1;
        int base = (1 << (d + 1)) - 1;
        int E = NTREES << (d + 1);
        gemm_dual<<<dim3(E/128, 4), 512, SM_DUAL>>>(
            p_s, p_rm, p_Pz, p_Ph, 1, 3, L, NT, base, E, wid, 0, base, out);
        GJob jr[1] = { { out, nullptr, p_Pr, nullptr, 5 } };
        launch_s(jr, 1, 3, L, NE_TREE, base - 1, E, wid, 0, base);
    }

    // ---- h_root ----
    {
        GJob jf[1] = { { p_s, out + (size_t)2 * NE_HALF * HID, p_Pf, nullptr, 7 } };
        launch_s(jf, 1, 6, 0, NT, 0, NTREES, wid, 0, 0);
    }

    // ---- top-down ----
    k_td_root<<<NTREES, HID>>>(wid, out);
    for (int d = 1; d <= 3; d++) {
        int pb = (1 << d) - 1;
        int Pn = NTREES << d;
        gemm_dual<<<dim3(Pn/128, 4), 512, SM_DUAL>>>(
            p_s, p_rm, p_Pz, p_Ph, 1, 3, d, NT, pb, Pn, wid, 1, pb, out);
        GJob ju[1] = { { p_M, nullptr, p_Pr, nullptr, 5 } };
        launch_s(ju, 1, 5, 0, 1, 0, Pn, wid, d, 0);
    }
}

// round 8
// speedup vs baseline: 1.0746x; 1.0746x over previous
#include <cuda_runtime.h>
#include <cuda_bf16.h>
#include <math.h>
#include <stdint.h>

#define HID     256
#define NT      31
#define NTREES  4096
#define NNODES  (NTREES*NT)       // 126976
#define NE_TREE 30
#define NE_HALF (NTREES*NE_TREE)  // 122880
#define VOCAB   780

// ---------------- scratch (static device globals; no allocation) ----------------
__device__ float g_s  [NNODES*HID];     // BU states
__device__ float g_rm [NNODES*HID];
__device__ float g_s2 [NNODES*HID];     // TD states (private -> BU/TD can overlap)
__device__ float g_rm2[NNODES*HID];
__device__ float g_M  [32768*HID];      // TD per-parent m
__device__ float g_T1 [32768*HID];      // BU z
__device__ float g_T2 [32768*HID];      // BU h(tanh)
__device__ float g_T1b[32768*HID];      // TD z
__device__ float g_T2b[32768*HID];      // TD h(tanh)
__device__ float g_Pz[VOCAB*HID];
__device__ float g_Ph[VOCAB*HID];
__device__ float g_Pr[VOCAB*HID];
__device__ float g_Pf[VOCAB*HID];
__device__ float g_M0 [VOCAB*HID];
__device__ float g_MU0[VOCAB*HID];
__device__ __nv_bfloat16 g_Whi[8*HID*HID];   // transposed [n][k] bf16 hi
__device__ __nv_bfloat16 g_Wlo[8*HID*HID];   // transposed [n][k] bf16 lo

__device__ __forceinline__ float sigf(float x){ return 1.0f/(1.0f+expf(-x)); }

__device__ __forceinline__ uint32_t smem_u32(const void* p){
    uint32_t a;
    asm("{ .reg .u64 t; cvta.to.shared.u64 t, %1; cvt.u32.u64 %0, t; }" : "=r"(a) : "l"(p));
    return a;
}
__device__ __forceinline__ void ldsm_x4(uint32_t a, uint32_t* r){
    asm volatile("ldmatrix.sync.aligned.m8n8.x4.shared.b16 {%0,%1,%2,%3}, [%4];"
        : "=r"(r[0]),"=r"(r[1]),"=r"(r[2]),"=r"(r[3]) : "r"(a));
}
__device__ __forceinline__ void mma_bf16(float* d, const uint32_t* a, const uint32_t* b){
    asm volatile("mma.sync.aligned.m16n8k16.row.col.f32.bf16.bf16.f32 "
        "{%0,%1,%2,%3}, {%4,%5,%6,%7}, {%8,%9}, {%0,%1,%2,%3};"
        : "+f"(d[0]),"+f"(d[1]),"+f"(d[2]),"+f"(d[3])
        : "r"(a[0]),"r"(a[1]),"r"(a[2]),"r"(a[3]), "r"(b[0]),"r"(b[1]));
}
__device__ __forceinline__ void cp16(uint32_t dst, const void* src){
    asm volatile("cp.async.cg.shared.global [%0], [%1], 16;" :: "r"(dst), "l"(src));
}
#define CP_COMMIT() asm volatile("cp.async.commit_group;" ::: "memory")
#define CP_WAIT0()  asm volatile("cp.async.wait_group 0;" ::: "memory")
#define SWZ(o) ((o) ^ (((o) >> 3) & 0x70))

__device__ __forceinline__ void cvt_split(float4 v, uint2& hi, uint2& lo){
    __nv_bfloat162 h01 = __floats2bfloat162_rn(v.x, v.y);
    __nv_bfloat162 h23 = __floats2bfloat162_rn(v.z, v.w);
    float lx = v.x - __bfloat162float(h01.x);
    float ly = v.y - __bfloat162float(h01.y);
    float lz = v.z - __bfloat162float(h23.x);
    float lw = v.w - __bfloat162float(h23.y);
    __nv_bfloat162 l01 = __floats2bfloat162_rn(lx, ly);
    __nv_bfloat162 l23 = __floats2bfloat162_rn(lz, lw);
    hi = make_uint2(*(uint32_t*)&h01, *(uint32_t*)&h23);
    lo = make_uint2(*(uint32_t*)&l01, *(uint32_t*)&l23);
}

// ==================================================================
// Pipelined bf16-split GEMM, tile 128x32, 256 thr (8 warps on M),
// grid (R/128, 8, nz). 2 stages x (A 16KB + W 4KB) = 40KB, 2 CTAs/SM.
// node(rg) = (rg>>aL)*aRS + aBase + (rg & ((1<<aL)-1))
// modes: 0 C=acc(+bias)            [bounds-checked]
//        1 C=sig (acc+P[wid[node]])
//        2 C=tanh(acc+P[wid[node]])
//        3 BU-R: r=sig(acc+P[wid[parent]]); pair-reduce m,m*r -> g_s/g_rm
//        5 TD-R: r0/r1=sig(acc+P[wid[child]]); write children s2/rm2
//        6 C=relu(acc+P[wid[node]]) [bounds-checked]
// ==================================================================
struct GJob {
    const float* A;
    float*       C;
    const float* P;
    const float* bias;
    int mat;
    int mode;
};

#define STAGE_B 20480
#define SM_SNG  (2*STAGE_B)

__global__ void __launch_bounds__(256,2) gemm_s(
    GJob j0, GJob j1, GJob j2, GJob j3,
    int aL, int aRS, int aBase, int R,
    const int* __restrict__ wid, int dlev, int base)
{
    extern __shared__ char sm[];
    const uint32_t sb = smem_u32(sm);
    const int tid = threadIdx.x, l = tid & 31, w = tid >> 5;
    const int row0 = blockIdx.x * 128, col0 = blockIdx.y * 32;
    const int aMask = (1 << aL) - 1;

    const GJob j = (blockIdx.z == 0) ? j0 : (blockIdx.z == 1) ? j1
                 : (blockIdx.z == 2) ? j2 : j3;
    const int mode = j.mode;

    // ---- A loader: 2 thr/row, each 4 float4 (16 floats) ----
    const int arow = tid >> 1, ahalf = tid & 1;
    const int argl = row0 + arow;
    const float* Asrc = nullptr;
    if (argl < R) {
        int an = ((argl >> aL) * aRS) + aBase + (argl & aMask);
        Asrc = j.A + (size_t)an * HID;
    }

    // ---- W loader: 1 cp16/thr/chunk ----
    const int wnr = tid >> 3, wu = tid & 7;
    const __nv_bfloat16* wsrc = ((wu < 4) ? g_Whi : g_Wlo)
        + (size_t)j.mat * HID * HID + (size_t)(col0 + wnr) * HID
        + (wu < 4 ? wu : wu - 4) * 8;
    const uint32_t wdst = SWZ((uint32_t)(wnr * 128 + wu * 16));

    // ---- epilogue prefetch: row ids + wid gathers ----
    int rgs[2];
    rgs[0] = row0 + w * 16 + (l >> 2);
    rgs[1] = rgs[0] + 8;
    int pwa[2] = {0, 0}, pwb[2] = {0, 0};
    #pragma unroll
    for (int i = 0; i < 2; i++) {
        int rg = rgs[i];
        if (mode == 1 || mode == 2 || mode == 6) {
            if (rg < R) {
                int nd = ((rg >> aL) * aRS) + aBase + (rg & aMask);
                pwa[i] = wid[nd];
            }
        } else if (mode == 3) {
            int tree = rg >> aL, jj = rg & aMask;
            pwa[i] = wid[tree * NT + ((base + jj - 1) >> 1)];
        } else if (mode == 5) {
            int m2 = (1 << dlev) - 1;
            int tree = rg >> dlev, q = rg & m2;
            int ch = tree * NT + 2 * (m2 + q) + 1;
            pwa[i] = wid[ch];
            pwb[i] = wid[ch + 1];
        }
    }

    float acc[4][4];
    #pragma unroll
    for (int a = 0; a < 4; a++)
        #pragma unroll
        for (int q = 0; q < 4; q++) acc[a][q] = 0.f;

    float4 av[4];
#define LDA(kc) do { \
    _Pragma("unroll") \
    for (int i2 = 0; i2 < 4; i2++) \
        av[i2] = Asrc ? *(const float4*)(Asrc + (kc)*32 + ahalf*16 + i2*4) \
                      : make_float4(0.f,0.f,0.f,0.f); \
} while(0)
#define STSA(st) do { \
    char* bp = sm + (st)*STAGE_B; \
    _Pragma("unroll") \
    for (int i2 = 0; i2 < 4; i2++) { \
        uint2 hi, lo; cvt_split(av[i2], hi, lo); \
        uint32_t ro = (uint32_t)(arow*128 + ahalf*32 + i2*8); \
        *(uint2*)(bp + SWZ(ro))      = hi; \
        *(uint2*)(bp + SWZ(ro + 64)) = lo; \
    } \
} while(0)
#define CPW(st, kc) do { \
    cp16(sb + (st)*STAGE_B + 16384 + wdst, wsrc + (kc)*32); \
} while(0)

    // prologue: fill stage 0
    LDA(0);
    CPW(0, 0); CP_COMMIT();
    STSA(0);

    #pragma unroll 1
    for (int kc = 0; kc < 8; kc++) {
        const int st = kc & 1;
        CP_WAIT0();
        __syncthreads();
        if (kc < 7) { CPW(st ^ 1, kc + 1); CP_COMMIT(); LDA(kc + 1); }

        const uint32_t sA = sb + st * STAGE_B, sW = sA + 16384;
        const int mi = l >> 3;
        #pragma unroll
        for (int ks = 0; ks < 2; ks++) {
            uint32_t ah[4], al2[4];
            {
                int rrow = w * 16 + (l & 15);
                int kb = ks * 16 + (l >> 4) * 8;
                ldsm_x4(sA + SWZ((uint32_t)(rrow * 128 + kb * 2)),      ah);
                ldsm_x4(sA + SWZ((uint32_t)(rrow * 128 + 64 + kb * 2)), al2);
            }
            #pragma unroll
            for (int p = 0; p < 2; p++) {
                int nrow = p * 16 + (mi >> 1) * 8 + (l & 7);
                int kb2 = ks * 16 + (mi & 1) * 8;
                uint32_t bh[4], bl[4];
                ldsm_x4(sW + SWZ((uint32_t)(nrow * 128 + kb2 * 2)),      bh);
                ldsm_x4(sW + SWZ((uint32_t)(nrow * 128 + 64 + kb2 * 2)), bl);
                mma_bf16(acc[2*p],   ah,  &bh[0]);
                mma_bf16(acc[2*p],   ah,  &bl[0]);
                mma_bf16(acc[2*p],   al2, &bh[0]);
                mma_bf16(acc[2*p+1], ah,  &bh[2]);
                mma_bf16(acc[2*p+1], ah,  &bl[2]);
                mma_bf16(acc[2*p+1], al2, &bh[2]);
            }
        }
        if (kc < 7) STSA(st ^ 1);
    }
#undef LDA
#undef STSA
#undef CPW

    // ---------------- fused epilogues ----------------
    #pragma unroll
    for (int i = 0; i < 2; i++) {
        int rg = rgs[i];
        if (mode == 0) {
            if (rg >= R) continue;
            float* crow = j.C + (size_t)rg * HID;
            #pragma unroll
            for (int ns = 0; ns < 4; ns++) {
                int c = col0 + ns * 8 + (l & 3) * 2;
                float v0 = acc[ns][i*2+0], v1 = acc[ns][i*2+1];
                if (j.bias) { v0 += j.bias[c]; v1 += j.bias[c+1]; }
                *(float2*)(crow + c) = make_float2(v0, v1);
            }
        } else if (mode == 1 || mode == 2 || mode == 6) {
            if (rg >= R) continue;
            const float* prow = j.P + (size_t)pwa[i] * HID;
            float* crow = j.C + (size_t)rg * HID;
            #pragma unroll
            for (int ns = 0; ns < 4; ns++) {
                int c = col0 + ns * 8 + (l & 3) * 2;
                float v0 = acc[ns][i*2+0] + prow[c];
                float v1 = acc[ns][i*2+1] + prow[c+1];
                if      (mode == 1) { v0 = sigf(v0);       v1 = sigf(v1); }
                else if (mode == 2) { v0 = tanhf(v0);      v1 = tanhf(v1); }
                else                { v0 = fmaxf(v0, 0.f); v1 = fmaxf(v1, 0.f); }
                *(float2*)(crow + c) = make_float2(v0, v1);
            }
        } else if (mode == 3) {
            int tree = rg >> aL, jj = rg & aMask;
            int node = tree * aRS + aBase + jj;               // A row (out edge)
            int parent = tree * NT + ((base + jj - 1) >> 1);
            const float* mrow = j.A + (size_t)node * HID;
            const float* prow = j.P + (size_t)pwa[i] * HID;
            float* ds = g_s  + (size_t)parent * HID;
            float* dr = g_rm + (size_t)parent * HID;
            #pragma unroll
            for (int ns = 0; ns < 4; ns++) {
                int c = col0 + ns * 8 + (l & 3) * 2;
                #pragma unroll
                for (int cc = 0; cc < 2; cc++) {
                    float r = sigf(acc[ns][i*2+cc] + prow[c+cc]);
                    float m = mrow[c+cc];
                    float mr = m * r;
                    float msum  = m  + __shfl_xor_sync(0xffffffffu, m, 4);
                    float mrsum = mr + __shfl_xor_sync(0xffffffffu, mr, 4);
                    if (!(l & 4)) { ds[c+cc] = msum; dr[c+cc] = mrsum; }
                }
            }
        } else { // mode 5
            int m2 = (1 << dlev) - 1;
            int tree = rg >> dlev, q = rg & m2;
            int ch = tree * NT + 2 * (m2 + q) + 1;
            const float* mrow = j.A + (size_t)rg * HID;       // g_M
            const float* p0 = j.P + (size_t)pwa[i] * HID;
            const float* p1 = j.P + (size_t)pwb[i] * HID;
            float* s0 = g_s2  + (size_t)ch * HID;
            float* r0 = g_rm2 + (size_t)ch * HID;
            #pragma unroll
            for (int ns = 0; ns < 4; ns++) {
                int c = col0 + ns * 8 + (l & 3) * 2;
                #pragma unroll
                for (int cc = 0; cc < 2; cc++) {
                    float a = acc[ns][i*2+cc];
                    float m = mrow[c+cc];
                    s0[c+cc]       = m;
                    s0[HID + c+cc] = m;
                    r0[c+cc]       = m * sigf(a + p0[c+cc]);
                    r0[HID + c+cc] = m * sigf(a + p1[c+cc]);
                }
            }
        }
    }
}

// ---------------- weight transpose + bf16 split prep ----------------
__global__ void k_prepw(const float* __restrict__ Wz, const float* __restrict__ Wh,
                        const float* __restrict__ Wr, const float* __restrict__ Ur,
                        const float* __restrict__ Wf)
{
    const float* src;
    switch (blockIdx.x) {
        case 0: src = Wz; break;            case 1: src = Wz + 256*HID; break;
        case 2: src = Wh; break;            case 3: src = Wh + 256*HID; break;
        case 4: src = Wr; break;            case 5: src = Ur; break;
        case 6: src = Wf; break;            default: src = Wf + 256*HID; break;
    }
    int n = threadIdx.x;
    size_t mb = (size_t)blockIdx.x * HID * HID;
    int k0 = blockIdx.y * 32;
    for (int k = k0; k < k0 + 32; k++) {
        float v = src[(size_t)k * HID + n];
        __nv_bfloat16 h = __float2bfloat16(v);
        float lo = v - __bfloat162float(h);
        g_Whi[mb + (size_t)n * HID + k] = h;
        g_Wlo[mb + (size_t)n * HID + k] = __float2bfloat16(lo);
    }
}

// ---------------- structural / elementwise kernels ----------------
__global__ void k_M0() {
    size_t o = (size_t)blockIdx.x * HID + threadIdx.x;
    g_M0[o] = sigf(g_Pz[o]) * tanhf(g_Ph[o]);
}

__global__ void k_bu_leaf(const int* __restrict__ wid, float* __restrict__ out) {
    int p = blockIdx.x, jl = threadIdx.x;
    int tree = p >> 3, q = p & 7;
    int pl = 7 + q;
    int parent = tree * NT + pl;
    int c0 = 2 * pl + 1;
    int child0 = tree * NT + c0;
    int w0 = wid[child0], w1 = wid[child0 + 1];
    float pr = g_Pr[(size_t)wid[parent] * HID + jl];
    float m0 = g_M0[(size_t)w0 * HID + jl];
    float m1 = g_M0[(size_t)w1 * HID + jl];
    float r0 = sigf(pr + g_MU0[(size_t)w0 * HID + jl]);
    float r1 = sigf(pr + g_MU0[(size_t)w1 * HID + jl]);
    size_t e0 = (size_t)(tree * NE_TREE + c0 - 1) * HID + jl;
    out[e0]       = m0;
    out[e0 + HID] = m1;
    size_t po = (size_t)parent * HID + jl;
    g_s[po]  = m0 + m1;
    g_rm[po] = m0 * r0 + m1 * r1;
}

__global__ void k_bu_M(int L, int base, float* __restrict__ out) {
    int e = blockIdx.x, jl = threadIdx.x;
    int tree = e >> L, jj = e & ((1 << L) - 1);
    int child = tree * NT + base + jj;
    size_t eo = (size_t)e * HID + jl;
    float z = g_T1[eo], h = g_T2[eo];
    float s = g_s[(size_t)child * HID + jl];
    out[(size_t)(tree * NE_TREE + base - 1 + jj) * HID + jl] = (1.0f - z) * s + z * h;
}

__global__ void k_td_root(const int* __restrict__ wid, float* __restrict__ out) {
    int tree = blockIdx.x, jl = threadIdx.x;
    int wr = wid[tree * NT];
    float m  = g_M0 [(size_t)wr * HID + jl];
    float mu = g_MU0[(size_t)wr * HID + jl];
    #pragma unroll
    for (int c = 1; c <= 2; c++) {
        int child = tree * NT + c;
        float r = sigf(g_Pr[(size_t)wid[child] * HID + jl] + mu);
        size_t co = (size_t)child * HID + jl;
        g_s2[co]  = m;
        g_rm2[co] = m * r;
        out[(size_t)(NE_HALF + tree * NE_TREE + c - 1) * HID + jl] = m;
    }
}

__global__ void k_td_M(int d, float* __restrict__ out) {
    int p = blockIdx.x, jl = threadIdx.x;
    int tree = p >> d, q = p & ((1 << d) - 1);
    int pl = (1 << d) - 1 + q;
    int parent = tree * NT + pl;
    size_t po = (size_t)p * HID + jl;
    float z = g_T1b[po], h = g_T2b[po];
    float s = g_s2[(size_t)parent * HID + jl];
    float m = (1.0f - z) * s + z * h;
    g_M[po] = m;
    size_t eid0 = (size_t)(NE_HALF + tree * NE_TREE + 2 * pl) * HID + jl;
    out[eid0]       = m;
    out[eid0 + HID] = m;
}

// ---------------- host ----------------
static inline void launch_g(const GJob* js, int nz,
                            int aL, int aRS, int aBase, int R,
                            const int* wid, int dlev, int base, cudaStream_t st)
{
    dim3 g((R + 127) / 128, 8, nz);
    gemm_s<<<g, 256, SM_SNG, st>>>(
        js[0], (nz>1)?js[1]:js[0], (nz>2)?js[2]:js[0], (nz>3)?js[3]:js[0],
        aL, aRS, aBase, R, wid, dlev, base);
}

extern "C" void kernel_launch(void* const* d_in, const int* in_sizes, int n_in,
                              void* d_out, int out_size)
{
    const int*   wid = (const int*)  d_in[0];
    const float* emb = (const float*)d_in[1];
    const float* Wz  = (const float*)d_in[2];
    const float* bz  = (const float*)d_in[3];
    const float* Wh  = (const float*)d_in[4];
    const float* bh  = (const float*)d_in[5];
    const float* Wr  = (const float*)d_in[6];
    const float* Ur  = (const float*)d_in[7];
    const float* bu  = (const float*)d_in[8];
    const float* Wf  = (const float*)d_in[9];
    const float* bf  = (const float*)d_in[10];
    float* out = (float*)d_out;

    float *p_s, *p_rm, *p_M, *p_Pz, *p_Ph, *p_Pr, *p_Pf, *p_M0, *p_MU0;
    float *p_s2, *p_rm2, *p_T1, *p_T2, *p_T1b, *p_T2b;
    cudaGetSymbolAddress((void**)&p_s,   g_s);
    cudaGetSymbolAddress((void**)&p_rm,  g_rm);
    cudaGetSymbolAddress((void**)&p_s2,  g_s2);
    cudaGetSymbolAddress((void**)&p_rm2, g_rm2);
    cudaGetSymbolAddress((void**)&p_M,   g_M);
    cudaGetSymbolAddress((void**)&p_T1,  g_T1);
    cudaGetSymbolAddress((void**)&p_T2,  g_T2);
    cudaGetSymbolAddress((void**)&p_T1b, g_T1b);
    cudaGetSymbolAddress((void**)&p_T2b, g_T2b);
    cudaGetSymbolAddress((void**)&p_Pz,  g_Pz);
    cudaGetSymbolAddress((void**)&p_Ph,  g_Ph);
    cudaGetSymbolAddress((void**)&p_Pr,  g_Pr);
    cudaGetSymbolAddress((void**)&p_Pf,  g_Pf);
    cudaGetSymbolAddress((void**)&p_M0,  g_M0);
    cudaGetSymbolAddress((void**)&p_MU0, g_MU0);

    cudaFuncSetAttribute(gemm_s, cudaFuncAttributeMaxDynamicSharedMemorySize, SM_SNG);

    // one-time stream/event setup (first call is the uncaptured correctness run)
    static cudaStream_t s_td = nullptr;
    static cudaEvent_t  ev_fork = nullptr, ev_join = nullptr;
    if (!s_td) {
        cudaStreamCreateWithFlags(&s_td, cudaStreamNonBlocking);
        cudaEventCreateWithFlags(&ev_fork, cudaEventDisableTiming);
        cudaEventCreateWithFlags(&ev_join, cudaEventDisableTiming);
    }

    // ---- prep: weights + vocab tables ----
    k_prepw<<<dim3(8, 8), 256>>>(Wz, Wh, Wr, Ur, Wf);
    {
        GJob js[4] = {
            { emb, p_Pz, nullptr, bz, 0, 0 },
            { emb, p_Ph, nullptr, bh, 2, 0 },
            { emb, p_Pr, nullptr, bu, 4, 0 },
            { emb, p_Pf, nullptr, bf, 6, 0 },
        };
        launch_g(js, 4, 0, 1, 0, VOCAB, wid, 0, 0, 0);
    }
    k_M0<<<VOCAB, HID>>>();
    {
        GJob js[1] = { { p_M0, p_MU0, nullptr, nullptr, 5, 0 } };
        launch_g(js, 1, 0, 1, 0, VOCAB, wid, 0, 0, 0);
    }

    // ---- fork: TD chain runs concurrently on s_td ----
    cudaEventRecord(ev_fork, 0);
    cudaStreamWaitEvent(s_td, ev_fork, 0);

    // ===== bottom-up (stream 0) =====
    k_bu_leaf<<<NTREES * 8, HID>>>(wid, out);
    for (int d = 2; d >= 0; d--) {
        int L = d + 1;
        int base = (1 << (d + 1)) - 1;
        int E = NTREES << (d + 1);
        GJob zh[2] = {
            { p_s,  p_T1, p_Pz, nullptr, 1, 1 },   // z = sig(Pz + s@Wzs)
            { p_rm, p_T2, p_Ph, nullptr, 3, 2 },   // h = tanh(Ph + rm@Whs)
        };
        launch_g(zh, 2, L, NT, base, E, wid, 0, base, 0);
        k_bu_M<<<E, HID>>>(L, base, out);
        GJob jr[1] = { { out, nullptr, p_Pr, nullptr, 5, 3 } };   // R + pair-reduce
        launch_g(jr, 1, L, NE_TREE, base - 1, E, wid, 0, base, 0);
    }
    {   // h_root
        GJob jf[1] = { { p_s, out + (size_t)2 * NE_HALF * HID, p_Pf, nullptr, 7, 6 } };
        launch_g(jf, 1, 0, NT, 0, NTREES, wid, 0, 0, 0);
    }

    // ===== top-down (s_td) =====
    k_td_root<<<NTREES, HID, 0, s_td>>>(wid, out);
    for (int d = 1; d <= 3; d++) {
        int pb = (1 << d) - 1;
        int Pn = NTREES << d;
        GJob zh[2] = {
            { p_s2,  p_T1b, p_Pz, nullptr, 1, 1 },
            { p_rm2, p_T2b, p_Ph, nullptr, 3, 2 },
        };
        launch_g(zh, 2, d, NT, pb, Pn, wid, 0, pb, s_td);
        k_td_M<<<Pn, HID, 0, s_td>>>(d, out);
        GJob ju[1] = { { p_M, nullptr, p_Pr, nullptr, 5, 5 } };   // R + child states
        launch_g(ju, 1, 0, 1, 0, Pn, wid, d, 0, s_td);
    }

    // ---- join ----
    cudaEventRecord(ev_join, s_td);
    cudaStreamWaitEvent(0, ev_join, 0);
}